// round 7
// baseline (speedup 1.0000x reference)
#include <cuda_runtime.h>
#include <cstdint>

#define BATCH   2048
#define RNK     32
#define H_INIT  256
#define H_DYN   512
#define D_DYN   98
#define D_INIT  96
#define NSTEP   31          // STEPS-1 RK4 steps

#define L2E2 2.885390081777927f   // 2*log2(e)

// Pre-transposed weights. [k][u] layout => lane-coalesced loads.
__device__ float g_WtDyn[D_DYN * H_DYN];
__device__ float g_WtInit[D_INIT * H_INIT];

__global__ void prep_kernel(const float* __restrict__ Wd1,
                            const float* __restrict__ Wi1) {
    int i = blockIdx.x * blockDim.x + threadIdx.x;
    if (i < D_DYN * H_DYN) {
        int k = i / H_DYN, u = i % H_DYN;
        g_WtDyn[i] = Wd1[u * D_DYN + k];
    }
    int j = i - D_DYN * H_DYN;
    if (j >= 0 && j < D_INIT * H_INIT) {
        int k = j / H_INIT, u = j % H_INIT;
        g_WtInit[j] = Wi1[u * D_INIT + k];
    }
}

__device__ __forceinline__ float tanhf_fast(float a) {
    float r; asm("tanh.approx.f32 %0, %1;" : "=f"(r) : "f"(a)); return r;
}
__device__ __forceinline__ float ex2f(float a) {
    float r; asm("ex2.approx.f32 %0, %1;" : "=f"(r) : "f"(a)); return r;
}
// FMA-pipe reciprocal: bit-trick seed + 2 Newton steps (~6e-5 rel err).
// Input w >= 1 here, so no edge cases.
__device__ __forceinline__ float rcp_fma(float w) {
    float y = __int_as_float(0x7EF311C3 - __float_as_int(w));
    y = y * fmaf(-w, y, 2.0f);
    y = y * fmaf(-w, y, 2.0f);
    return y;
}

// 2 warps/block; each warp owns TWO samples as independent full-width
// dataflows (16 units/lane). Units 0-5/lane use MUFU tanh (rt~16);
// units 6-15 use ex2 (rt 8) + FMA-pipe Newton reciprocal, splitting the
// activation cost across MUFU and FMA pipes.
__global__ void __launch_bounds__(64) node_kernel(
    const int*   __restrict__ b_i_raw,   // int32 or int64 (sniffed)
    const float* __restrict__ b_t_n,
    const float* __restrict__ U0,
    const float* __restrict__ U1,
    const float* __restrict__ U2,
    const float* __restrict__ bi1,
    const float* __restrict__ Wi2,
    const float* __restrict__ bi2,
    const float* __restrict__ bd1,
    const float* __restrict__ Wd2,
    const float* __restrict__ bd2,
    float* __restrict__ out)
{
    __shared__ float uv[4][96];          // 2 warps x 2 samples
    const int lane = threadIdx.x & 31;
    const int wib  = threadIdx.x >> 5;   // warp in block
    const int wid  = blockIdx.x * 2 + wib;
    const int sA   = wid * 2;
    const int sB   = sA + 1;
    const int ub   = lane * 4;

    // --- index dtype sniff: int64 rows have zero high words ---
    bool is64 = ((b_i_raw[1] | b_i_raw[3] | b_i_raw[5]) == 0);
    int iA0, iA1, iA2, iB0, iB1, iB2;
    if (is64) {
        iA0 = b_i_raw[(sA * 3 + 0) * 2];
        iA1 = b_i_raw[(sA * 3 + 1) * 2];
        iA2 = b_i_raw[(sA * 3 + 2) * 2];
        iB0 = b_i_raw[(sB * 3 + 0) * 2];
        iB1 = b_i_raw[(sB * 3 + 1) * 2];
        iB2 = b_i_raw[(sB * 3 + 2) * 2];
    } else {
        iA0 = b_i_raw[sA * 3 + 0];
        iA1 = b_i_raw[sA * 3 + 1];
        iA2 = b_i_raw[sA * 3 + 2];
        iB0 = b_i_raw[sB * 3 + 0];
        iB1 = b_i_raw[sB * 3 + 1];
        iB2 = b_i_raw[sB * 3 + 2];
    }

    // --- gather Uvec (96) into shared for both samples ---
    float* uvA = uv[wib * 2 + 0];
    float* uvB = uv[wib * 2 + 1];
    uvA[lane]      = U0[(size_t)iA0 * RNK + lane];
    uvA[32 + lane] = U1[(size_t)iA1 * RNK + lane];
    uvA[64 + lane] = U2[(size_t)iA2 * RNK + lane];
    uvB[lane]      = U0[(size_t)iB0 * RNK + lane];
    uvB[32 + lane] = U1[(size_t)iB1 * RNK + lane];
    uvB[64 + lane] = U2[(size_t)iB2 * RNK + lane];
    __syncwarp();

    // ======================= dyn-net precompute =======================
    // c[u] = bd1[u] + Wd1[u,2:]·Uvec   for both samples; weights shared.
    float cA[16], cB[16];
    #pragma unroll
    for (int q = 0; q < 4; q++) {
        float4 bv = *(const float4*)(bd1 + q * 128 + ub);
        cA[q*4+0] = bv.x; cA[q*4+1] = bv.y; cA[q*4+2] = bv.z; cA[q*4+3] = bv.w;
        cB[q*4+0] = bv.x; cB[q*4+1] = bv.y; cB[q*4+2] = bv.z; cB[q*4+3] = bv.w;
    }
    #pragma unroll 2
    for (int k = 0; k < 96; k++) {
        float ukA = uvA[k];
        float ukB = uvB[k];
        const float* row = g_WtDyn + (k + 2) * H_DYN + ub;
        #pragma unroll
        for (int q = 0; q < 4; q++) {
            float4 wv = *(const float4*)(row + q * 128);
            cA[q*4+0] = fmaf(wv.x, ukA, cA[q*4+0]);
            cA[q*4+1] = fmaf(wv.y, ukA, cA[q*4+1]);
            cA[q*4+2] = fmaf(wv.z, ukA, cA[q*4+2]);
            cA[q*4+3] = fmaf(wv.w, ukA, cA[q*4+3]);
            cB[q*4+0] = fmaf(wv.x, ukB, cB[q*4+0]);
            cB[q*4+1] = fmaf(wv.y, ukB, cB[q*4+1]);
            cB[q*4+2] = fmaf(wv.z, ukB, cB[q*4+2]);
            cB[q*4+3] = fmaf(wv.w, ukB, cB[q*4+3]);
        }
    }

    // ======================= init net: x0 for both =======================
    float aiA[8], aiB[8];
    #pragma unroll
    for (int q = 0; q < 2; q++) {
        float4 bv = *(const float4*)(bi1 + q * 128 + ub);
        aiA[q*4+0] = bv.x; aiA[q*4+1] = bv.y; aiA[q*4+2] = bv.z; aiA[q*4+3] = bv.w;
        aiB[q*4+0] = bv.x; aiB[q*4+1] = bv.y; aiB[q*4+2] = bv.z; aiB[q*4+3] = bv.w;
    }
    #pragma unroll 2
    for (int k = 0; k < 96; k++) {
        float ukA = uvA[k];
        float ukB = uvB[k];
        const float* row = g_WtInit + k * H_INIT + ub;
        #pragma unroll
        for (int q = 0; q < 2; q++) {
            float4 wv = *(const float4*)(row + q * 128);
            aiA[q*4+0] = fmaf(wv.x, ukA, aiA[q*4+0]);
            aiA[q*4+1] = fmaf(wv.y, ukA, aiA[q*4+1]);
            aiA[q*4+2] = fmaf(wv.z, ukA, aiA[q*4+2]);
            aiA[q*4+3] = fmaf(wv.w, ukA, aiA[q*4+3]);
            aiB[q*4+0] = fmaf(wv.x, ukB, aiB[q*4+0]);
            aiB[q*4+1] = fmaf(wv.y, ukB, aiB[q*4+1]);
            aiB[q*4+2] = fmaf(wv.z, ukB, aiB[q*4+2]);
            aiB[q*4+3] = fmaf(wv.w, ukB, aiB[q*4+3]);
        }
    }
    float pA = 0.f, pB = 0.f;
    #pragma unroll
    for (int q = 0; q < 2; q++) {
        float4 wv = *(const float4*)(Wi2 + q * 128 + ub);
        pA = fmaf(tanhf_fast(aiA[q*4+0]), wv.x, pA);
        pB = fmaf(tanhf_fast(aiB[q*4+0]), wv.x, pB);
        pA = fmaf(tanhf_fast(aiA[q*4+1]), wv.y, pA);
        pB = fmaf(tanhf_fast(aiB[q*4+1]), wv.y, pB);
        pA = fmaf(tanhf_fast(aiA[q*4+2]), wv.z, pA);
        pB = fmaf(tanhf_fast(aiB[q*4+2]), wv.z, pB);
        pA = fmaf(tanhf_fast(aiA[q*4+3]), wv.w, pA);
        pB = fmaf(tanhf_fast(aiB[q*4+3]), wv.w, pB);
    }
    #pragma unroll
    for (int off = 16; off > 0; off >>= 1) {
        pA += __shfl_xor_sync(0xffffffffu, pA, off);
        pB += __shfl_xor_sync(0xffffffffu, pB, off);
    }

    float xA = pA + bi2[0];
    float xB = pB + bi2[0];
    const float bd2v = bd2[0];
    const float sTA = b_t_n[sA];
    const float sTB = b_t_n[sB];

    // ======================= shared dyn weights =======================
    float w0l[16], w1l[16], w2l[16];
    #pragma unroll
    for (int q = 0; q < 4; q++) {
        float4 a0 = *(const float4*)(g_WtDyn + 0 * H_DYN + q * 128 + ub);
        float4 a1 = *(const float4*)(g_WtDyn + 1 * H_DYN + q * 128 + ub);
        float4 a2 = *(const float4*)(Wd2 + q * 128 + ub);
        w0l[q*4+0] = a0.x; w0l[q*4+1] = a0.y; w0l[q*4+2] = a0.z; w0l[q*4+3] = a0.w;
        w1l[q*4+0] = a1.x; w1l[q*4+1] = a1.y; w1l[q*4+2] = a1.z; w1l[q*4+3] = a1.w;
        w2l[q*4+0] = a2.x; w2l[q*4+1] = a2.y; w2l[q*4+2] = a2.z; w2l[q*4+3] = a2.w;
    }

    // --- fold ex2-path scaling into per-unit weights (units 6..15) ---
    // ex2 path: tanh(z) = 1 - 2/(2^(L2E2*z)+1); contribution to the sum is
    // w2 - 2*w2*y. The "w2" constant part is folded into sumw2 (acc init);
    // w2l becomes -2*w2 for those units.
    float sumw2 = 0.f;
    #pragma unroll
    for (int i = 6; i < 16; i++) {
        w0l[i] *= L2E2;
        w1l[i] *= L2E2;
        cA[i]  *= L2E2;
        cB[i]  *= L2E2;
        sumw2 += w2l[i];
        w2l[i] *= -2.f;
    }

    // ======================= RK4 loop (dual sample) =======================
    // a_u = e_u + w1_u*x with e_u = c_u + w0_u*(t*sT) hoisted per stage time
    // (k2/k3 share t). dyn = (reduce(sum) + bd2) * sT.
    float eA[16], eB[16];
    auto build_e = [&](float t) {
        float tsA = t * sTA;
        float tsB = t * sTB;
        #pragma unroll
        for (int i = 0; i < 16; i++) {
            eA[i] = fmaf(w0l[i], tsA, cA[i]);
            eB[i] = fmaf(w0l[i], tsB, cB[i]);
        }
    };
    float kAo, kBo;
    auto feval2 = [&](float xvA, float xvB) {
        float accA0 = sumw2, accA1 = 0.f, accB0 = sumw2, accB1 = 0.f;
        // MUFU-tanh path: units 0..5
        #pragma unroll
        for (int i = 0; i < 6; i += 2) {
            float aA0 = fmaf(w1l[i],   xvA, eA[i]);
            float aB0 = fmaf(w1l[i],   xvB, eB[i]);
            float aA1 = fmaf(w1l[i+1], xvA, eA[i+1]);
            float aB1 = fmaf(w1l[i+1], xvB, eB[i+1]);
            accA0 = fmaf(tanhf_fast(aA0), w2l[i],   accA0);
            accB0 = fmaf(tanhf_fast(aB0), w2l[i],   accB0);
            accA1 = fmaf(tanhf_fast(aA1), w2l[i+1], accA1);
            accB1 = fmaf(tanhf_fast(aB1), w2l[i+1], accB1);
        }
        // ex2 + FMA-Newton path: units 6..15 (w2l pre-multiplied by -2)
        #pragma unroll
        for (int i = 6; i < 16; i += 2) {
            float aA0 = fmaf(w1l[i],   xvA, eA[i]);
            float aB0 = fmaf(w1l[i],   xvB, eB[i]);
            float aA1 = fmaf(w1l[i+1], xvA, eA[i+1]);
            float aB1 = fmaf(w1l[i+1], xvB, eB[i+1]);
            float wA0 = ex2f(aA0) + 1.f;
            float wB0 = ex2f(aB0) + 1.f;
            float wA1 = ex2f(aA1) + 1.f;
            float wB1 = ex2f(aB1) + 1.f;
            accA0 = fmaf(rcp_fma(wA0), w2l[i],   accA0);
            accB0 = fmaf(rcp_fma(wB0), w2l[i],   accB0);
            accA1 = fmaf(rcp_fma(wA1), w2l[i+1], accA1);
            accB1 = fmaf(rcp_fma(wB1), w2l[i+1], accB1);
        }
        float rA = accA0 + accA1;
        float rB = accB0 + accB1;
        #pragma unroll
        for (int off = 16; off > 0; off >>= 1) {
            rA += __shfl_xor_sync(0xffffffffu, rA, off);
            rB += __shfl_xor_sync(0xffffffffu, rB, off);
        }
        kAo = (rA + bd2v) * sTA;
        kBo = (rB + bd2v) * sTB;
    };

    const float hh = 1.f / 31.f;
    #pragma unroll 1
    for (int stp = 0; stp < NSTEP; stp++) {
        float t0 = (float)stp * hh;
        build_e(t0);
        feval2(xA, xB);
        float kA1 = kAo, kB1 = kBo;
        build_e(t0 + 0.5f * hh);
        feval2(fmaf(0.5f * hh, kA1, xA), fmaf(0.5f * hh, kB1, xB));
        float kA2 = kAo, kB2 = kBo;
        feval2(fmaf(0.5f * hh, kA2, xA), fmaf(0.5f * hh, kB2, xB)); // same t
        float kA3 = kAo, kB3 = kBo;
        build_e(t0 + hh);
        feval2(fmaf(hh, kA3, xA), fmaf(hh, kB3, xB));
        xA += (hh / 6.f) * (kA1 + 2.f * (kA2 + kA3) + kAo);
        xB += (hh / 6.f) * (kB1 + 2.f * (kB2 + kB3) + kBo);
    }

    if (lane == 0) {
        out[sA] = xA;
        out[sB] = xB;
    }
}

extern "C" void kernel_launch(void* const* d_in, const int* in_sizes, int n_in,
                              void* d_out, int out_size) {
    const int*   b_i  = (const int*)  d_in[0];
    const float* b_t  = (const float*)d_in[1];
    const float* U0   = (const float*)d_in[2];
    const float* U1   = (const float*)d_in[3];
    const float* U2   = (const float*)d_in[4];
    const float* Wi1  = (const float*)d_in[5];
    const float* bi1  = (const float*)d_in[6];
    const float* Wi2  = (const float*)d_in[7];
    const float* bi2  = (const float*)d_in[8];
    const float* Wd1  = (const float*)d_in[9];
    const float* bd1  = (const float*)d_in[10];
    const float* Wd2  = (const float*)d_in[11];
    const float* bd2  = (const float*)d_in[12];

    int tot = D_DYN * H_DYN + D_INIT * H_INIT;
    prep_kernel<<<(tot + 255) / 256, 256>>>(Wd1, Wi1);
    // 512 blocks x 64 threads: 2 warps/block, 2 samples/warp -> 2048 samples
    node_kernel<<<BATCH / 4, 64>>>(b_i, b_t, U0, U1, U2,
                                   bi1, Wi2, bi2, bd1, Wd2, bd2,
                                   (float*)d_out);
}

// round 9
// speedup vs baseline: 1.1759x; 1.1759x over previous
#include <cuda_runtime.h>
#include <cuda_fp16.h>
#include <cstdint>

#define BATCH   2048
#define RNK     32
#define H_INIT  256
#define H_DYN   512
#define D_DYN   98
#define D_INIT  96
#define NSTEP   31          // STEPS-1 RK4 steps

// Pre-transposed weights. [k][u] layout => lane-coalesced loads.
__device__ float g_WtDyn[D_DYN * H_DYN];
__device__ float g_WtInit[D_INIT * H_INIT];

__global__ void prep_kernel(const float* __restrict__ Wd1,
                            const float* __restrict__ Wi1) {
    int i = blockIdx.x * blockDim.x + threadIdx.x;
    if (i < D_DYN * H_DYN) {
        int k = i / H_DYN, u = i % H_DYN;
        g_WtDyn[i] = Wd1[u * D_DYN + k];
    }
    int j = i - D_DYN * H_DYN;
    if (j >= 0 && j < D_INIT * H_INIT) {
        int k = j / H_INIT, u = j % H_INIT;
        g_WtInit[j] = Wi1[u * D_INIT + k];
    }
}

__device__ __forceinline__ float tanhf_fast(float a) {
    float r; asm("tanh.approx.f32 %0, %1;" : "=f"(r) : "f"(a)); return r;
}
// Two tanh in one MUFU op (f16x2). Inputs here are small (|a| < ~3),
// far inside f16 range.
__device__ __forceinline__ __half2 htanh2(__half2 a) {
    uint32_t ain = *reinterpret_cast<uint32_t*>(&a);
    uint32_t rout;
    asm("tanh.approx.f16x2 %0, %1;" : "=r"(rout) : "r"(ain));
    return *reinterpret_cast<__half2*>(&rout);
}

// 2 warps/block; each warp owns TWO samples as independent full-width
// dataflows (16 units/lane). The (A,B) sample pair shares each MUFU tanh
// via f16x2: f32 activation -> pack -> tanh.approx.f16x2 -> HFMA2 acc.
__global__ void __launch_bounds__(64) node_kernel(
    const int*   __restrict__ b_i_raw,   // int32 or int64 (sniffed)
    const float* __restrict__ b_t_n,
    const float* __restrict__ U0,
    const float* __restrict__ U1,
    const float* __restrict__ U2,
    const float* __restrict__ bi1,
    const float* __restrict__ Wi2,
    const float* __restrict__ bi2,
    const float* __restrict__ bd1,
    const float* __restrict__ Wd2,
    const float* __restrict__ bd2,
    float* __restrict__ out)
{
    __shared__ float uv[4][96];          // 2 warps x 2 samples
    const int lane = threadIdx.x & 31;
    const int wib  = threadIdx.x >> 5;   // warp in block
    const int wid  = blockIdx.x * 2 + wib;
    const int sA   = wid * 2;
    const int sB   = sA + 1;
    const int ub   = lane * 4;

    // --- index dtype sniff: int64 rows have zero high words ---
    bool is64 = ((b_i_raw[1] | b_i_raw[3] | b_i_raw[5]) == 0);
    int iA0, iA1, iA2, iB0, iB1, iB2;
    if (is64) {
        iA0 = b_i_raw[(sA * 3 + 0) * 2];
        iA1 = b_i_raw[(sA * 3 + 1) * 2];
        iA2 = b_i_raw[(sA * 3 + 2) * 2];
        iB0 = b_i_raw[(sB * 3 + 0) * 2];
        iB1 = b_i_raw[(sB * 3 + 1) * 2];
        iB2 = b_i_raw[(sB * 3 + 2) * 2];
    } else {
        iA0 = b_i_raw[sA * 3 + 0];
        iA1 = b_i_raw[sA * 3 + 1];
        iA2 = b_i_raw[sA * 3 + 2];
        iB0 = b_i_raw[sB * 3 + 0];
        iB1 = b_i_raw[sB * 3 + 1];
        iB2 = b_i_raw[sB * 3 + 2];
    }

    // --- gather Uvec (96) into shared for both samples ---
    float* uvA = uv[wib * 2 + 0];
    float* uvB = uv[wib * 2 + 1];
    uvA[lane]      = U0[(size_t)iA0 * RNK + lane];
    uvA[32 + lane] = U1[(size_t)iA1 * RNK + lane];
    uvA[64 + lane] = U2[(size_t)iA2 * RNK + lane];
    uvB[lane]      = U0[(size_t)iB0 * RNK + lane];
    uvB[32 + lane] = U1[(size_t)iB1 * RNK + lane];
    uvB[64 + lane] = U2[(size_t)iB2 * RNK + lane];
    __syncwarp();

    // ======================= dyn-net precompute =======================
    // c[u] = bd1[u] + Wd1[u,2:]·Uvec   for both samples; weights shared.
    float cA[16], cB[16];
    #pragma unroll
    for (int q = 0; q < 4; q++) {
        float4 bv = *(const float4*)(bd1 + q * 128 + ub);
        cA[q*4+0] = bv.x; cA[q*4+1] = bv.y; cA[q*4+2] = bv.z; cA[q*4+3] = bv.w;
        cB[q*4+0] = bv.x; cB[q*4+1] = bv.y; cB[q*4+2] = bv.z; cB[q*4+3] = bv.w;
    }
    #pragma unroll 2
    for (int k = 0; k < 96; k++) {
        float ukA = uvA[k];
        float ukB = uvB[k];
        const float* row = g_WtDyn + (k + 2) * H_DYN + ub;
        #pragma unroll
        for (int q = 0; q < 4; q++) {
            float4 wv = *(const float4*)(row + q * 128);
            cA[q*4+0] = fmaf(wv.x, ukA, cA[q*4+0]);
            cA[q*4+1] = fmaf(wv.y, ukA, cA[q*4+1]);
            cA[q*4+2] = fmaf(wv.z, ukA, cA[q*4+2]);
            cA[q*4+3] = fmaf(wv.w, ukA, cA[q*4+3]);
            cB[q*4+0] = fmaf(wv.x, ukB, cB[q*4+0]);
            cB[q*4+1] = fmaf(wv.y, ukB, cB[q*4+1]);
            cB[q*4+2] = fmaf(wv.z, ukB, cB[q*4+2]);
            cB[q*4+3] = fmaf(wv.w, ukB, cB[q*4+3]);
        }
    }

    // ======================= init net: x0 for both (f32 path) ============
    float aiA[8], aiB[8];
    #pragma unroll
    for (int q = 0; q < 2; q++) {
        float4 bv = *(const float4*)(bi1 + q * 128 + ub);
        aiA[q*4+0] = bv.x; aiA[q*4+1] = bv.y; aiA[q*4+2] = bv.z; aiA[q*4+3] = bv.w;
        aiB[q*4+0] = bv.x; aiB[q*4+1] = bv.y; aiB[q*4+2] = bv.z; aiB[q*4+3] = bv.w;
    }
    #pragma unroll 2
    for (int k = 0; k < 96; k++) {
        float ukA = uvA[k];
        float ukB = uvB[k];
        const float* row = g_WtInit + k * H_INIT + ub;
        #pragma unroll
        for (int q = 0; q < 2; q++) {
            float4 wv = *(const float4*)(row + q * 128);
            aiA[q*4+0] = fmaf(wv.x, ukA, aiA[q*4+0]);
            aiA[q*4+1] = fmaf(wv.y, ukA, aiA[q*4+1]);
            aiA[q*4+2] = fmaf(wv.z, ukA, aiA[q*4+2]);
            aiA[q*4+3] = fmaf(wv.w, ukA, aiA[q*4+3]);
            aiB[q*4+0] = fmaf(wv.x, ukB, aiB[q*4+0]);
            aiB[q*4+1] = fmaf(wv.y, ukB, aiB[q*4+1]);
            aiB[q*4+2] = fmaf(wv.z, ukB, aiB[q*4+2]);
            aiB[q*4+3] = fmaf(wv.w, ukB, aiB[q*4+3]);
        }
    }
    float pA = 0.f, pB = 0.f;
    #pragma unroll
    for (int q = 0; q < 2; q++) {
        float4 wv = *(const float4*)(Wi2 + q * 128 + ub);
        pA = fmaf(tanhf_fast(aiA[q*4+0]), wv.x, pA);
        pB = fmaf(tanhf_fast(aiB[q*4+0]), wv.x, pB);
        pA = fmaf(tanhf_fast(aiA[q*4+1]), wv.y, pA);
        pB = fmaf(tanhf_fast(aiB[q*4+1]), wv.y, pB);
        pA = fmaf(tanhf_fast(aiA[q*4+2]), wv.z, pA);
        pB = fmaf(tanhf_fast(aiB[q*4+2]), wv.z, pB);
        pA = fmaf(tanhf_fast(aiA[q*4+3]), wv.w, pA);
        pB = fmaf(tanhf_fast(aiB[q*4+3]), wv.w, pB);
    }
    #pragma unroll
    for (int off = 16; off > 0; off >>= 1) {
        pA += __shfl_xor_sync(0xffffffffu, pA, off);
        pB += __shfl_xor_sync(0xffffffffu, pB, off);
    }

    float xA = pA + bi2[0];
    float xB = pB + bi2[0];
    const float bd2v = bd2[0];
    const float sTA = b_t_n[sA];
    const float sTB = b_t_n[sB];

    // ======================= shared dyn weights =======================
    float w0l[16], w1l[16];
    __half2 w2p[16];                      // (w2_u, w2_u) packed
    #pragma unroll
    for (int q = 0; q < 4; q++) {
        float4 a0 = *(const float4*)(g_WtDyn + 0 * H_DYN + q * 128 + ub);
        float4 a1 = *(const float4*)(g_WtDyn + 1 * H_DYN + q * 128 + ub);
        float4 a2 = *(const float4*)(Wd2 + q * 128 + ub);
        w0l[q*4+0] = a0.x; w0l[q*4+1] = a0.y; w0l[q*4+2] = a0.z; w0l[q*4+3] = a0.w;
        w1l[q*4+0] = a1.x; w1l[q*4+1] = a1.y; w1l[q*4+2] = a1.z; w1l[q*4+3] = a1.w;
        w2p[q*4+0] = __floats2half2_rn(a2.x, a2.x);
        w2p[q*4+1] = __floats2half2_rn(a2.y, a2.y);
        w2p[q*4+2] = __floats2half2_rn(a2.z, a2.z);
        w2p[q*4+3] = __floats2half2_rn(a2.w, a2.w);
    }

    // ======================= RK4 loop (dual sample) =======================
    // a_u = e_u + w1_u*x with e_u = c_u + w0_u*(t*sT) hoisted per stage time
    // (k2/k3 share t). Pair (A,B) in f16x2 for the tanh + accumulate.
    float eA[16], eB[16];
    auto build_e = [&](float t) {
        float tsA = t * sTA;
        float tsB = t * sTB;
        #pragma unroll
        for (int i = 0; i < 16; i++) {
            eA[i] = fmaf(w0l[i], tsA, cA[i]);
            eB[i] = fmaf(w0l[i], tsB, cB[i]);
        }
    };
    float kAo, kBo;
    auto feval2 = [&](float xvA, float xvB) {
        __half2 hacc0 = __float2half2_rn(0.f);
        __half2 hacc1 = __float2half2_rn(0.f);
        #pragma unroll
        for (int i = 0; i < 16; i += 2) {
            float aA0 = fmaf(w1l[i],   xvA, eA[i]);
            float aB0 = fmaf(w1l[i],   xvB, eB[i]);
            float aA1 = fmaf(w1l[i+1], xvA, eA[i+1]);
            float aB1 = fmaf(w1l[i+1], xvB, eB[i+1]);
            __half2 h0 = __floats2half2_rn(aA0, aB0);
            __half2 h1 = __floats2half2_rn(aA1, aB1);
            __half2 t0 = htanh2(h0);
            __half2 t1 = htanh2(h1);
            hacc0 = __hfma2(t0, w2p[i],   hacc0);
            hacc1 = __hfma2(t1, w2p[i+1], hacc1);
        }
        float2 s0 = __half22float2(hacc0);
        float2 s1 = __half22float2(hacc1);
        float rA = s0.x + s1.x;
        float rB = s0.y + s1.y;
        #pragma unroll
        for (int off = 16; off > 0; off >>= 1) {
            rA += __shfl_xor_sync(0xffffffffu, rA, off);
            rB += __shfl_xor_sync(0xffffffffu, rB, off);
        }
        kAo = (rA + bd2v) * sTA;
        kBo = (rB + bd2v) * sTB;
    };

    const float hh = 1.f / 31.f;
    #pragma unroll 1
    for (int stp = 0; stp < NSTEP; stp++) {
        float t0 = (float)stp * hh;
        build_e(t0);
        feval2(xA, xB);
        float kA1 = kAo, kB1 = kBo;
        build_e(t0 + 0.5f * hh);
        feval2(fmaf(0.5f * hh, kA1, xA), fmaf(0.5f * hh, kB1, xB));
        float kA2 = kAo, kB2 = kBo;
        feval2(fmaf(0.5f * hh, kA2, xA), fmaf(0.5f * hh, kB2, xB)); // same t
        float kA3 = kAo, kB3 = kBo;
        build_e(t0 + hh);
        feval2(fmaf(hh, kA3, xA), fmaf(hh, kB3, xB));
        xA += (hh / 6.f) * (kA1 + 2.f * (kA2 + kA3) + kAo);
        xB += (hh / 6.f) * (kB1 + 2.f * (kB2 + kB3) + kBo);
    }

    if (lane == 0) {
        out[sA] = xA;
        out[sB] = xB;
    }
}

extern "C" void kernel_launch(void* const* d_in, const int* in_sizes, int n_in,
                              void* d_out, int out_size) {
    const int*   b_i  = (const int*)  d_in[0];
    const float* b_t  = (const float*)d_in[1];
    const float* U0   = (const float*)d_in[2];
    const float* U1   = (const float*)d_in[3];
    const float* U2   = (const float*)d_in[4];
    const float* Wi1  = (const float*)d_in[5];
    const float* bi1  = (const float*)d_in[6];
    const float* Wi2  = (const float*)d_in[7];
    const float* bi2  = (const float*)d_in[8];
    const float* Wd1  = (const float*)d_in[9];
    const float* bd1  = (const float*)d_in[10];
    const float* Wd2  = (const float*)d_in[11];
    const float* bd2  = (const float*)d_in[12];

    int tot = D_DYN * H_DYN + D_INIT * H_INIT;
    prep_kernel<<<(tot + 255) / 256, 256>>>(Wd1, Wi1);
    // 512 blocks x 64 threads: 2 warps/block, 2 samples/warp -> 2048 samples
    node_kernel<<<BATCH / 4, 64>>>(b_i, b_t, U0, U1, U2,
                                   bi1, Wi2, bi2, bd1, Wd2, bd2,
                                   (float*)d_out);
}

// round 10
// speedup vs baseline: 1.2681x; 1.0784x over previous
#include <cuda_runtime.h>
#include <cstdint>

#define BATCH   2048
#define RNK     32
#define H_INIT  256
#define H_DYN   512
#define D_DYN   98
#define D_INIT  96
#define NSTEP   31          // STEPS-1 RK4 steps

// Pre-transposed weights. [k][u] layout => lane-coalesced loads.
__device__ float g_WtDyn[D_DYN * H_DYN];
__device__ float g_WtInit[D_INIT * H_INIT];

__global__ void prep_kernel(const float* __restrict__ Wd1,
                            const float* __restrict__ Wi1) {
    int i = blockIdx.x * blockDim.x + threadIdx.x;
    if (i < D_DYN * H_DYN) {
        int k = i / H_DYN, u = i % H_DYN;
        g_WtDyn[i] = Wd1[u * D_DYN + k];
    }
    int j = i - D_DYN * H_DYN;
    if (j >= 0 && j < D_INIT * H_INIT) {
        int k = j / H_INIT, u = j % H_INIT;
        g_WtInit[j] = Wi1[u * D_INIT + k];
    }
}

__device__ __forceinline__ float tanhf_fast(float a) {
    float r; asm("tanh.approx.f32 %0, %1;" : "=f"(r) : "f"(a)); return r;
}

// ---- Blackwell packed f32x2 helpers (FFMA2: 2 fp32 FMAs in 1 instr) ----
__device__ __forceinline__ unsigned long long pk2(float lo, float hi) {
    unsigned long long d;
    asm("mov.b64 %0, {%1, %2};" : "=l"(d) : "f"(lo), "f"(hi));
    return d;
}
__device__ __forceinline__ void upk2(float& lo, float& hi, unsigned long long v) {
    asm("mov.b64 {%0, %1}, %2;" : "=f"(lo), "=f"(hi) : "l"(v));
}
__device__ __forceinline__ unsigned long long fma2(unsigned long long a,
                                                   unsigned long long b,
                                                   unsigned long long c) {
    unsigned long long r;
    asm("fma.rn.f32x2 %0, %1, %2, %3;" : "=l"(r) : "l"(a), "l"(b), "l"(c));
    return r;
}

// 2 warps/block; each warp owns TWO samples (A,B) as packed f32x2 lanes:
// activation / accumulate / build_e run as FFMA2 (one instr per pair),
// tanh stays f32 per sample.
__global__ void __launch_bounds__(64) node_kernel(
    const int*   __restrict__ b_i_raw,   // int32 or int64 (sniffed)
    const float* __restrict__ b_t_n,
    const float* __restrict__ U0,
    const float* __restrict__ U1,
    const float* __restrict__ U2,
    const float* __restrict__ bi1,
    const float* __restrict__ Wi2,
    const float* __restrict__ bi2,
    const float* __restrict__ bd1,
    const float* __restrict__ Wd2,
    const float* __restrict__ bd2,
    float* __restrict__ out)
{
    __shared__ float uv[4][96];          // 2 warps x 2 samples
    const int lane = threadIdx.x & 31;
    const int wib  = threadIdx.x >> 5;   // warp in block
    const int wid  = blockIdx.x * 2 + wib;
    const int sA   = wid * 2;
    const int sB   = sA + 1;
    const int ub   = lane * 4;

    // --- index dtype sniff: int64 rows have zero high words ---
    bool is64 = ((b_i_raw[1] | b_i_raw[3] | b_i_raw[5]) == 0);
    int iA0, iA1, iA2, iB0, iB1, iB2;
    if (is64) {
        iA0 = b_i_raw[(sA * 3 + 0) * 2];
        iA1 = b_i_raw[(sA * 3 + 1) * 2];
        iA2 = b_i_raw[(sA * 3 + 2) * 2];
        iB0 = b_i_raw[(sB * 3 + 0) * 2];
        iB1 = b_i_raw[(sB * 3 + 1) * 2];
        iB2 = b_i_raw[(sB * 3 + 2) * 2];
    } else {
        iA0 = b_i_raw[sA * 3 + 0];
        iA1 = b_i_raw[sA * 3 + 1];
        iA2 = b_i_raw[sA * 3 + 2];
        iB0 = b_i_raw[sB * 3 + 0];
        iB1 = b_i_raw[sB * 3 + 1];
        iB2 = b_i_raw[sB * 3 + 2];
    }

    // --- gather Uvec (96) into shared for both samples ---
    float* uvA = uv[wib * 2 + 0];
    float* uvB = uv[wib * 2 + 1];
    uvA[lane]      = U0[(size_t)iA0 * RNK + lane];
    uvA[32 + lane] = U1[(size_t)iA1 * RNK + lane];
    uvA[64 + lane] = U2[(size_t)iA2 * RNK + lane];
    uvB[lane]      = U0[(size_t)iB0 * RNK + lane];
    uvB[32 + lane] = U1[(size_t)iB1 * RNK + lane];
    uvB[64 + lane] = U2[(size_t)iB2 * RNK + lane];
    __syncwarp();

    // ======================= dyn-net precompute (packed) =================
    // cp[u] = (cA_u, cB_u) = bd1[u] + Wd1[u,2:]·Uvec ; FFMA2 with (w,w).
    unsigned long long cp[16];
    #pragma unroll
    for (int q = 0; q < 4; q++) {
        float4 bv = *(const float4*)(bd1 + q * 128 + ub);
        cp[q*4+0] = pk2(bv.x, bv.x);
        cp[q*4+1] = pk2(bv.y, bv.y);
        cp[q*4+2] = pk2(bv.z, bv.z);
        cp[q*4+3] = pk2(bv.w, bv.w);
    }
    #pragma unroll 2
    for (int k = 0; k < 96; k++) {
        unsigned long long ukp = pk2(uvA[k], uvB[k]);
        const float* row = g_WtDyn + (k + 2) * H_DYN + ub;
        #pragma unroll
        for (int q = 0; q < 4; q++) {
            float4 wv = *(const float4*)(row + q * 128);
            cp[q*4+0] = fma2(pk2(wv.x, wv.x), ukp, cp[q*4+0]);
            cp[q*4+1] = fma2(pk2(wv.y, wv.y), ukp, cp[q*4+1]);
            cp[q*4+2] = fma2(pk2(wv.z, wv.z), ukp, cp[q*4+2]);
            cp[q*4+3] = fma2(pk2(wv.w, wv.w), ukp, cp[q*4+3]);
        }
    }

    // ======================= init net: x0 for both (packed) ==============
    unsigned long long aip[8];
    #pragma unroll
    for (int q = 0; q < 2; q++) {
        float4 bv = *(const float4*)(bi1 + q * 128 + ub);
        aip[q*4+0] = pk2(bv.x, bv.x);
        aip[q*4+1] = pk2(bv.y, bv.y);
        aip[q*4+2] = pk2(bv.z, bv.z);
        aip[q*4+3] = pk2(bv.w, bv.w);
    }
    #pragma unroll 2
    for (int k = 0; k < 96; k++) {
        unsigned long long ukp = pk2(uvA[k], uvB[k]);
        const float* row = g_WtInit + k * H_INIT + ub;
        #pragma unroll
        for (int q = 0; q < 2; q++) {
            float4 wv = *(const float4*)(row + q * 128);
            aip[q*4+0] = fma2(pk2(wv.x, wv.x), ukp, aip[q*4+0]);
            aip[q*4+1] = fma2(pk2(wv.y, wv.y), ukp, aip[q*4+1]);
            aip[q*4+2] = fma2(pk2(wv.z, wv.z), ukp, aip[q*4+2]);
            aip[q*4+3] = fma2(pk2(wv.w, wv.w), ukp, aip[q*4+3]);
        }
    }
    float pA = 0.f, pB = 0.f;
    #pragma unroll
    for (int q = 0; q < 2; q++) {
        float4 wv = *(const float4*)(Wi2 + q * 128 + ub);
        float aA, aB;
        upk2(aA, aB, aip[q*4+0]);
        pA = fmaf(tanhf_fast(aA), wv.x, pA); pB = fmaf(tanhf_fast(aB), wv.x, pB);
        upk2(aA, aB, aip[q*4+1]);
        pA = fmaf(tanhf_fast(aA), wv.y, pA); pB = fmaf(tanhf_fast(aB), wv.y, pB);
        upk2(aA, aB, aip[q*4+2]);
        pA = fmaf(tanhf_fast(aA), wv.z, pA); pB = fmaf(tanhf_fast(aB), wv.z, pB);
        upk2(aA, aB, aip[q*4+3]);
        pA = fmaf(tanhf_fast(aA), wv.w, pA); pB = fmaf(tanhf_fast(aB), wv.w, pB);
    }
    #pragma unroll
    for (int off = 16; off > 0; off >>= 1) {
        pA += __shfl_xor_sync(0xffffffffu, pA, off);
        pB += __shfl_xor_sync(0xffffffffu, pB, off);
    }

    float xA = pA + bi2[0];
    float xB = pB + bi2[0];
    const float bd2v = bd2[0];
    const float sTA = b_t_n[sA];
    const float sTB = b_t_n[sB];

    // ======================= shared dyn weights (packed (w,w)) ===========
    unsigned long long w0p[16], w1p[16], w2p[16];
    #pragma unroll
    for (int q = 0; q < 4; q++) {
        float4 a0 = *(const float4*)(g_WtDyn + 0 * H_DYN + q * 128 + ub);
        float4 a1 = *(const float4*)(g_WtDyn + 1 * H_DYN + q * 128 + ub);
        float4 a2 = *(const float4*)(Wd2 + q * 128 + ub);
        w0p[q*4+0] = pk2(a0.x, a0.x); w0p[q*4+1] = pk2(a0.y, a0.y);
        w0p[q*4+2] = pk2(a0.z, a0.z); w0p[q*4+3] = pk2(a0.w, a0.w);
        w1p[q*4+0] = pk2(a1.x, a1.x); w1p[q*4+1] = pk2(a1.y, a1.y);
        w1p[q*4+2] = pk2(a1.z, a1.z); w1p[q*4+3] = pk2(a1.w, a1.w);
        w2p[q*4+0] = pk2(a2.x, a2.x); w2p[q*4+1] = pk2(a2.y, a2.y);
        w2p[q*4+2] = pk2(a2.z, a2.z); w2p[q*4+3] = pk2(a2.w, a2.w);
    }

    // ======================= RK4 loop (packed dual sample) ===============
    // ep[u] = cp[u] + w0p[u]*(tsA,tsB); a = ep[u] + w1p[u]*(xA,xB);
    // tanh per component (f32 MUFU); acc via FFMA2 with w2p.
    unsigned long long ep[16];
    auto build_e = [&](float t) {
        unsigned long long tsp = pk2(t * sTA, t * sTB);
        #pragma unroll
        for (int i = 0; i < 16; i++)
            ep[i] = fma2(w0p[i], tsp, cp[i]);
    };
    float kAo, kBo;
    auto feval2 = [&](float xvA, float xvB) {
        unsigned long long xp = pk2(xvA, xvB);
        unsigned long long acc0 = 0ull, acc1 = 0ull;
        #pragma unroll
        for (int i = 0; i < 16; i += 2) {
            unsigned long long ap0 = fma2(w1p[i],   xp, ep[i]);
            unsigned long long ap1 = fma2(w1p[i+1], xp, ep[i+1]);
            float aA0, aB0, aA1, aB1;
            upk2(aA0, aB0, ap0);
            upk2(aA1, aB1, ap1);
            unsigned long long tp0 = pk2(tanhf_fast(aA0), tanhf_fast(aB0));
            unsigned long long tp1 = pk2(tanhf_fast(aA1), tanhf_fast(aB1));
            acc0 = fma2(tp0, w2p[i],   acc0);
            acc1 = fma2(tp1, w2p[i+1], acc1);
        }
        float rA0, rB0, rA1, rB1;
        upk2(rA0, rB0, acc0);
        upk2(rA1, rB1, acc1);
        float rA = rA0 + rA1;
        float rB = rB0 + rB1;
        #pragma unroll
        for (int off = 16; off > 0; off >>= 1) {
            rA += __shfl_xor_sync(0xffffffffu, rA, off);
            rB += __shfl_xor_sync(0xffffffffu, rB, off);
        }
        kAo = (rA + bd2v) * sTA;
        kBo = (rB + bd2v) * sTB;
    };

    const float hh = 1.f / 31.f;
    #pragma unroll 1
    for (int stp = 0; stp < NSTEP; stp++) {
        float t0 = (float)stp * hh;
        build_e(t0);
        feval2(xA, xB);
        float kA1 = kAo, kB1 = kBo;
        build_e(t0 + 0.5f * hh);
        feval2(fmaf(0.5f * hh, kA1, xA), fmaf(0.5f * hh, kB1, xB));
        float kA2 = kAo, kB2 = kBo;
        feval2(fmaf(0.5f * hh, kA2, xA), fmaf(0.5f * hh, kB2, xB)); // same t
        float kA3 = kAo, kB3 = kBo;
        build_e(t0 + hh);
        feval2(fmaf(hh, kA3, xA), fmaf(hh, kB3, xB));
        xA += (hh / 6.f) * (kA1 + 2.f * (kA2 + kA3) + kAo);
        xB += (hh / 6.f) * (kB1 + 2.f * (kB2 + kB3) + kBo);
    }

    if (lane == 0) {
        out[sA] = xA;
        out[sB] = xB;
    }
}

extern "C" void kernel_launch(void* const* d_in, const int* in_sizes, int n_in,
                              void* d_out, int out_size) {
    const int*   b_i  = (const int*)  d_in[0];
    const float* b_t  = (const float*)d_in[1];
    const float* U0   = (const float*)d_in[2];
    const float* U1   = (const float*)d_in[3];
    const float* U2   = (const float*)d_in[4];
    const float* Wi1  = (const float*)d_in[5];
    const float* bi1  = (const float*)d_in[6];
    const float* Wi2  = (const float*)d_in[7];
    const float* bi2  = (const float*)d_in[8];
    const float* Wd1  = (const float*)d_in[9];
    const float* bd1  = (const float*)d_in[10];
    const float* Wd2  = (const float*)d_in[11];
    const float* bd2  = (const float*)d_in[12];

    int tot = D_DYN * H_DYN + D_INIT * H_INIT;
    prep_kernel<<<(tot + 255) / 256, 256>>>(Wd1, Wi1);
    // 512 blocks x 64 threads: 2 warps/block, 2 samples/warp -> 2048 samples
    node_kernel<<<BATCH / 4, 64>>>(b_i, b_t, U0, U1, U2,
                                   bi1, Wi2, bi2, bd1, Wd2, bd2,
                                   (float*)d_out);
}